// round 3
// baseline (speedup 1.0000x reference)
#include <cuda_runtime.h>
#include <cuda_bf16.h>
#include <cstdint>

// GraphSAGE 2-layer, D=64, fp32 — CSR-gather formulation.
//
//   layer: out = h @ W_self + mean_{in}(h) @ W_neigh + b
//   h1 = relu(layer1(x)); out = layer2(h1)
//
// Strategy: build CSR (dst -> list of src) ONCE per launch with int atomics,
// then aggregate each layer by per-node gather (no float atomics), then a
// fused mean+dual-GEMM combine with weights staged in shared.
//
// Launch sequence (8 kernels, all graph-capturable, zero runtime API calls):
//   1 zero_cnt   2 hist   3 scan(1 block)   4 fill
//   5 gather<x>  6 combine(relu, ->h1)  7 gather<h1>  8 combine(->out)

#define D 64
#define MAXN 50048
#define MAXE 850000
#define SCAN_THREADS 1024

__device__ float g_sum[MAXN * D];     // per-layer: neighbor MEAN (gather writes mean directly)
__device__ float g_h1[MAXN * D];      // layer-1 activations
__device__ int   g_cnt[MAXN];         // in-degree (histogram)
__device__ int   g_rowstart[MAXN];    // CSR exclusive offsets
__device__ int   g_cursor[MAXN];      // fill cursors
__device__ int   g_edge[MAXE];        // CSR column (src) indices

// ---------------------------------------------------------------------------
__global__ void zero_cnt_kernel(int n) {
    int i = blockIdx.x * blockDim.x + threadIdx.x;
    if (i < n) g_cnt[i] = 0;
}

// ---------------------------------------------------------------------------
__global__ void hist_kernel(const int* __restrict__ dst, int E) {
    int e = blockIdx.x * blockDim.x + threadIdx.x;
    if (e < E) atomicAdd(&g_cnt[__ldg(dst + e)], 1);
}

// ---------------------------------------------------------------------------
// Single-block exclusive scan of g_cnt -> g_rowstart (+ copy to g_cursor).
// Each thread owns a contiguous run of ceil(n/1024) elements.
// ---------------------------------------------------------------------------
__global__ void __launch_bounds__(SCAN_THREADS)
scan_kernel(int n) {
    __shared__ int s[SCAN_THREADS];
    int t = threadIdx.x;
    int items = (n + SCAN_THREADS - 1) / SCAN_THREADS;
    int lo = t * items;
    int hi = min(n, lo + items);

    int sum = 0;
    for (int i = lo; i < hi; i++) sum += g_cnt[i];
    s[t] = sum;
    __syncthreads();

    // Hillis–Steele inclusive scan over thread totals.
    for (int off = 1; off < SCAN_THREADS; off <<= 1) {
        int v = (t >= off) ? s[t - off] : 0;
        __syncthreads();
        s[t] += v;
        __syncthreads();
    }
    int base = (t == 0) ? 0 : s[t - 1];   // exclusive prefix of this thread's run

    for (int i = lo; i < hi; i++) {
        g_rowstart[i] = base;
        g_cursor[i]   = base;
        base += g_cnt[i];
    }
}

// ---------------------------------------------------------------------------
__global__ void fill_kernel(const int* __restrict__ src,
                            const int* __restrict__ dst, int E) {
    int e = blockIdx.x * blockDim.x + threadIdx.x;
    if (e < E) {
        int d = __ldg(dst + e);
        int p = atomicAdd(&g_cursor[d], 1);
        g_edge[p] = __ldg(src + e);
    }
}

// ---------------------------------------------------------------------------
// Gather-aggregate: warp per node; each lane owns 2 consecutive floats
// (float2 at column lane*2). Accumulate neighbor rows in registers,
// divide by degree, write MEAN into g_sum. No float atomics.
// ---------------------------------------------------------------------------
template <bool FROM_H1>
__global__ void __launch_bounds__(256)
gather_kernel(const float* __restrict__ h_in, int n) {
    const float* __restrict__ h = FROM_H1 ? (const float*)g_h1 : h_in;

    int warp = (blockIdx.x * blockDim.x + threadIdx.x) >> 5;
    if (warp >= n) return;
    int lane = threadIdx.x & 31;

    int start = g_rowstart[warp];
    int deg   = g_cnt[warp];

    const float2* __restrict__ base = reinterpret_cast<const float2*>(h);
    float ax = 0.f, ay = 0.f;

    int i = 0;
    // 4-way unroll for memory-level parallelism.
    for (; i + 4 <= deg; i += 4) {
        int s0 = __ldg(g_edge + start + i + 0);
        int s1 = __ldg(g_edge + start + i + 1);
        int s2 = __ldg(g_edge + start + i + 2);
        int s3 = __ldg(g_edge + start + i + 3);
        float2 v0 = __ldg(base + (size_t)s0 * 32 + lane);
        float2 v1 = __ldg(base + (size_t)s1 * 32 + lane);
        float2 v2 = __ldg(base + (size_t)s2 * 32 + lane);
        float2 v3 = __ldg(base + (size_t)s3 * 32 + lane);
        ax += v0.x + v1.x + v2.x + v3.x;
        ay += v0.y + v1.y + v2.y + v3.y;
    }
    for (; i < deg; i++) {
        int s = __ldg(g_edge + start + i);
        float2 v = __ldg(base + (size_t)s * 32 + lane);
        ax += v.x; ay += v.y;
    }

    float inv = 1.0f / fmaxf((float)deg, 1.0f);
    float2 m; m.x = ax * inv; m.y = ay * inv;
    reinterpret_cast<float2*>(g_sum)[(size_t)warp * 32 + lane] = m;
}

// ---------------------------------------------------------------------------
// Fused combine: out = h@W_self + mean@W_neigh + b  [+ relu]
// Block = 256 threads = 16 nodes x 16 col-groups (4 cols).
// ---------------------------------------------------------------------------
template <bool RELU, bool FROM_H1, bool TO_H1>
__global__ void __launch_bounds__(256)
combine_kernel(const float* __restrict__ h_in,
               const float* __restrict__ Wself,
               const float* __restrict__ Wneigh,
               const float* __restrict__ bias,
               float* __restrict__ out_in, int n) {
    const float* __restrict__ h = FROM_H1 ? (const float*)g_h1 : h_in;
    float* __restrict__ out     = TO_H1 ? (float*)g_h1 : out_in;

    __shared__ float sWs[D * D];
    __shared__ float sWn[D * D];
    __shared__ float sX[16 * D];
    __shared__ float sM[16 * D];

    int tid = threadIdx.x;
    int node0 = blockIdx.x * 16;

    for (int i = tid; i < D * D / 4; i += 256) {
        reinterpret_cast<float4*>(sWs)[i] =
            reinterpret_cast<const float4*>(Wself)[i];
        reinterpret_cast<float4*>(sWn)[i] =
            reinterpret_cast<const float4*>(Wneigh)[i];
    }
    for (int i = tid; i < 16 * D / 4; i += 256) {
        int nl = i >> 4;
        int k4 = i & 15;
        int node = node0 + nl;
        if (node < n) {
            reinterpret_cast<float4*>(sX)[i] =
                reinterpret_cast<const float4*>(h + (size_t)node * D)[k4];
            reinterpret_cast<float4*>(sM)[i] =
                reinterpret_cast<const float4*>(g_sum + (size_t)node * D)[k4];
        } else {
            reinterpret_cast<float4*>(sX)[i] = make_float4(0.f, 0.f, 0.f, 0.f);
            reinterpret_cast<float4*>(sM)[i] = make_float4(0.f, 0.f, 0.f, 0.f);
        }
    }
    __syncthreads();

    int nl = tid >> 4;
    int cg = tid & 15;
    int c0 = cg * 4;

    float a0 = __ldg(bias + c0 + 0);
    float a1 = __ldg(bias + c0 + 1);
    float a2 = __ldg(bias + c0 + 2);
    float a3 = __ldg(bias + c0 + 3);

    const float* xr = sX + nl * D;
    const float* mr = sM + nl * D;

#pragma unroll
    for (int k = 0; k < D; k++) {
        float xv = xr[k];
        float mv = mr[k];
        float4 ws = *reinterpret_cast<const float4*>(sWs + k * D + c0);
        float4 wn = *reinterpret_cast<const float4*>(sWn + k * D + c0);
        a0 += xv * ws.x + mv * wn.x;
        a1 += xv * ws.y + mv * wn.y;
        a2 += xv * ws.z + mv * wn.z;
        a3 += xv * ws.w + mv * wn.w;
    }

    int node = node0 + nl;
    if (node < n) {
        if (RELU) {
            a0 = fmaxf(a0, 0.f); a1 = fmaxf(a1, 0.f);
            a2 = fmaxf(a2, 0.f); a3 = fmaxf(a3, 0.f);
        }
        *reinterpret_cast<float4*>(out + (size_t)node * D + c0) =
            make_float4(a0, a1, a2, a3);
    }
}

// ---------------------------------------------------------------------------
extern "C" void kernel_launch(void* const* d_in, const int* in_sizes, int n_in,
                              void* d_out, int out_size) {
    const float* x        = (const float*)d_in[0];
    const int*   src      = (const int*)d_in[1];
    const int*   dst      = (const int*)d_in[2];
    const float* W1_self  = (const float*)d_in[3];
    const float* W1_neigh = (const float*)d_in[4];
    const float* b1       = (const float*)d_in[5];
    const float* W2_self  = (const float*)d_in[6];
    const float* W2_neigh = (const float*)d_in[7];
    const float* b2       = (const float*)d_in[8];
    float* out = (float*)d_out;

    int n = in_sizes[0] / D;
    int E = in_sizes[1];

    int eb = (E + 255) / 256;
    int nb = (n + 255) / 256;
    int gb = (n * 32 + 255) / 256;     // warp per node
    int cb = (n + 15) / 16;

    // ---- CSR build (shared by both layers) ----
    zero_cnt_kernel<<<nb, 256>>>(n);
    hist_kernel<<<eb, 256>>>(dst, E);
    scan_kernel<<<1, SCAN_THREADS>>>(n);
    fill_kernel<<<eb, 256>>>(src, dst, E);

    // ---- layer 1 ----  (x -> g_h1, relu)
    gather_kernel<false><<<gb, 256>>>(x, n);
    combine_kernel<true, false, true>
        <<<cb, 256>>>(x, W1_self, W1_neigh, b1, nullptr, n);

    // ---- layer 2 ----  (g_h1 -> out)
    gather_kernel<true><<<gb, 256>>>(nullptr, n);
    combine_kernel<false, true, false>
        <<<cb, 256>>>(nullptr, W2_self, W2_neigh, b2, out, n);
}

// round 4
// speedup vs baseline: 1.5863x; 1.5863x over previous
#include <cuda_runtime.h>
#include <cuda_bf16.h>
#include <cstdint>

// GraphSAGE 2-layer, D=64, fp32.
//   layer: out = h @ W_self + mean_{in}(h) @ W_neigh + b
//   h1 = relu(layer1(x)); out = layer2(h1)
//
// R4: R2 scatter-RED structure (219us baseline) + rewritten combine:
//   - register tile 4 nodes x 4 cols per thread, 64 nodes per block
//   - only weights in shared (32KB); x/mean rows streamed from global (L2)
//   - packed fma.rn.f32x2 accumulation (2x fp32 FMA throughput, exact)

#define D 64
#define MAXN 50048

__device__ float g_sum[MAXN * D];   // segment sums (scatter) -> means consumed by combine
__device__ float g_deg[MAXN];       // in-degrees
__device__ float g_h1[MAXN * D];    // layer-1 activations

typedef unsigned long long u64;

__device__ __forceinline__ u64 pk2(float a, float b) {
    u64 r;
    asm("mov.b64 %0, {%1, %2};" : "=l"(r)
        : "r"(__float_as_uint(a)), "r"(__float_as_uint(b)));
    return r;
}
__device__ __forceinline__ void upk2(u64 v, float& a, float& b) {
    unsigned int x, y;
    asm("mov.b64 {%0, %1}, %2;" : "=r"(x), "=r"(y) : "l"(v));
    a = __uint_as_float(x);
    b = __uint_as_float(y);
}
__device__ __forceinline__ u64 fma2(u64 a, u64 b, u64 c) {
    u64 d;
    asm("fma.rn.f32x2 %0, %1, %2, %3;" : "=l"(d) : "l"(a), "l"(b), "l"(c));
    return d;
}

// ---------------------------------------------------------------------------
__global__ void zero_kernel(int n, int zero_deg) {
    int total4 = n * (D / 4);
    for (int i = blockIdx.x * blockDim.x + threadIdx.x; i < total4;
         i += gridDim.x * blockDim.x) {
        reinterpret_cast<float4*>(g_sum)[i] = make_float4(0.f, 0.f, 0.f, 0.f);
    }
    if (zero_deg) {
        for (int i = blockIdx.x * blockDim.x + threadIdx.x; i < n;
             i += gridDim.x * blockDim.x) {
            g_deg[i] = 0.f;
        }
    }
}

// ---------------------------------------------------------------------------
// Edge scatter: 16 threads per edge, each moves one float4 chunk.
// ---------------------------------------------------------------------------
template <bool FROM_H1, bool COUNT_DEG>
__global__ void __launch_bounds__(256)
scatter_kernel(const float* __restrict__ h_in,
               const int* __restrict__ src,
               const int* __restrict__ dst,
               int E) {
    const float* __restrict__ h = FROM_H1 ? (const float*)g_h1 : h_in;

    long long idx = (long long)blockIdx.x * blockDim.x + threadIdx.x;
    int e = (int)(idx >> 4);
    if (e >= E) return;
    int c = ((int)idx & 15) * 4;

    int s = __ldg(src + e);
    int d = __ldg(dst + e);

    float4 v = *reinterpret_cast<const float4*>(h + (size_t)s * D + c);
    float* p = g_sum + (size_t)d * D + c;
    asm volatile("red.global.add.v4.f32 [%0], {%1,%2,%3,%4};"
                 :: "l"(p), "f"(v.x), "f"(v.y), "f"(v.z), "f"(v.w)
                 : "memory");
    if (COUNT_DEG && c == 0) {
        asm volatile("red.global.add.f32 [%0], %1;"
                     :: "l"(g_deg + d), "f"(1.0f) : "memory");
    }
}

// ---------------------------------------------------------------------------
// Combine v2: out = h@W_self + (sum/deg)@W_neigh + b [+relu]
// Block: 256 threads = 16 col-groups x 16 node-groups; node-group = 4 nodes.
// 64 nodes per block. Thread computes 4 nodes x 4 cols with f32x2 packs.
// ---------------------------------------------------------------------------
template <bool RELU, bool FROM_H1, bool TO_H1>
__global__ void __launch_bounds__(256, 2)
combine_kernel(const float* __restrict__ h_in,
               const float* __restrict__ Wself,
               const float* __restrict__ Wneigh,
               const float* __restrict__ bias,
               float* __restrict__ out_in, int n) {
    const float* __restrict__ h = FROM_H1 ? (const float*)g_h1 : h_in;
    float* __restrict__ out     = TO_H1 ? (float*)g_h1 : out_in;

    __shared__ float sWs[D * D];   // 16 KB
    __shared__ float sWn[D * D];   // 16 KB

    int tid = threadIdx.x;
    for (int i = tid; i < D * D / 4; i += 256) {
        reinterpret_cast<float4*>(sWs)[i] =
            reinterpret_cast<const float4*>(Wself)[i];
        reinterpret_cast<float4*>(sWn)[i] =
            reinterpret_cast<const float4*>(Wneigh)[i];
    }
    __syncthreads();

    int cg = tid & 15;           // column group -> cols c0..c0+3
    int c0 = cg * 4;
    int ng = tid >> 4;           // node group  -> 4 nodes
    int nbase = blockIdx.x * 64 + ng * 4;

    // Per-node validity + inverse degree.
    bool valid[4];
    float invd[4];
#pragma unroll
    for (int i = 0; i < 4; i++) {
        valid[i] = (nbase + i) < n;
        invd[i] = valid[i] ? (1.0f / fmaxf(g_deg[nbase + i], 1.0f)) : 0.f;
    }

    u64 b01 = pk2(__ldg(bias + c0 + 0), __ldg(bias + c0 + 1));
    u64 b23 = pk2(__ldg(bias + c0 + 2), __ldg(bias + c0 + 3));

    u64 acc[4][2];
#pragma unroll
    for (int i = 0; i < 4; i++) { acc[i][0] = b01; acc[i][1] = b23; }

#pragma unroll 4
    for (int k0 = 0; k0 < D; k0 += 4) {
        // 4 nodes x 4 k-values of x and sum (from global; L2-resident,
        // lane-deduplicated by the coalescer across the 16 col-groups).
        float4 xv[4], mv[4];
#pragma unroll
        for (int i = 0; i < 4; i++) {
            if (valid[i]) {
                xv[i] = *reinterpret_cast<const float4*>(
                    h + (size_t)(nbase + i) * D + k0);
                float4 sv = *reinterpret_cast<const float4*>(
                    g_sum + (size_t)(nbase + i) * D + k0);
                mv[i] = make_float4(sv.x * invd[i], sv.y * invd[i],
                                    sv.z * invd[i], sv.w * invd[i]);
            } else {
                xv[i] = make_float4(0.f, 0.f, 0.f, 0.f);
                mv[i] = make_float4(0.f, 0.f, 0.f, 0.f);
            }
        }

#pragma unroll
        for (int j = 0; j < 4; j++) {
            int k = k0 + j;
            float4 ws = *reinterpret_cast<const float4*>(sWs + k * D + c0);
            float4 wn = *reinterpret_cast<const float4*>(sWn + k * D + c0);
            u64 ws01 = pk2(ws.x, ws.y), ws23 = pk2(ws.z, ws.w);
            u64 wn01 = pk2(wn.x, wn.y), wn23 = pk2(wn.z, wn.w);
#pragma unroll
            for (int i = 0; i < 4; i++) {
                float xk = (j == 0) ? xv[i].x : (j == 1) ? xv[i].y
                          : (j == 2) ? xv[i].z : xv[i].w;
                float mk = (j == 0) ? mv[i].x : (j == 1) ? mv[i].y
                          : (j == 2) ? mv[i].z : mv[i].w;
                u64 xx = pk2(xk, xk);
                u64 mm = pk2(mk, mk);
                acc[i][0] = fma2(xx, ws01, acc[i][0]);
                acc[i][0] = fma2(mm, wn01, acc[i][0]);
                acc[i][1] = fma2(xx, ws23, acc[i][1]);
                acc[i][1] = fma2(mm, wn23, acc[i][1]);
            }
        }
    }

#pragma unroll
    for (int i = 0; i < 4; i++) {
        if (!valid[i]) continue;
        float a0, a1, a2, a3;
        upk2(acc[i][0], a0, a1);
        upk2(acc[i][1], a2, a3);
        if (RELU) {
            a0 = fmaxf(a0, 0.f); a1 = fmaxf(a1, 0.f);
            a2 = fmaxf(a2, 0.f); a3 = fmaxf(a3, 0.f);
        }
        *reinterpret_cast<float4*>(out + (size_t)(nbase + i) * D + c0) =
            make_float4(a0, a1, a2, a3);
    }
}

// ---------------------------------------------------------------------------
extern "C" void kernel_launch(void* const* d_in, const int* in_sizes, int n_in,
                              void* d_out, int out_size) {
    const float* x        = (const float*)d_in[0];
    const int*   src      = (const int*)d_in[1];
    const int*   dst      = (const int*)d_in[2];
    const float* W1_self  = (const float*)d_in[3];
    const float* W1_neigh = (const float*)d_in[4];
    const float* b1       = (const float*)d_in[5];
    const float* W2_self  = (const float*)d_in[6];
    const float* W2_neigh = (const float*)d_in[7];
    const float* b2       = (const float*)d_in[8];
    float* out = (float*)d_out;

    int n = in_sizes[0] / D;
    int E = in_sizes[1];

    int zblocks = 1024;
    long long sc_items = (long long)E * 16;
    int sc_blocks = (int)((sc_items + 255) / 256);
    int cb_blocks = (n + 63) / 64;

    // ---- layer 1 ----  (x -> g_h1, relu)
    zero_kernel<<<zblocks, 256>>>(n, 1);
    scatter_kernel<false, true><<<sc_blocks, 256>>>(x, src, dst, E);
    combine_kernel<true, false, true>
        <<<cb_blocks, 256>>>(x, W1_self, W1_neigh, b1, nullptr, n);

    // ---- layer 2 ----  (g_h1 -> out)
    zero_kernel<<<zblocks, 256>>>(n, 0);
    scatter_kernel<true, false><<<sc_blocks, 256>>>(nullptr, src, dst, E);
    combine_kernel<false, true, false>
        <<<cb_blocks, 256>>>(nullptr, W2_self, W2_neigh, b2, out, n);
}